// round 2
// baseline (speedup 1.0000x reference)
#include <cuda_runtime.h>
#include <math.h>
#include <stdint.h>

// ---------------- problem constants ----------------
#define T_TOK   8192
#define H_DIM   1024
#define E_NUM   8
#define F_DIM   4096
#define MAX_TILES 136              // sum_e ceil(cnt_e/128) <= (16384 + 8*127)/128 < 136
#define MAX_ROWS  (MAX_TILES * 128)

// ---------------- device scratch (no allocations allowed) ----------------
__device__ float g_h[(size_t)MAX_ROWS * F_DIM];        // ~285 MB: silu(xWg)*(xWu) per routed row
__device__ float g_partial[(size_t)MAX_ROWS * H_DIM];  // ~71 MB: unscaled down-proj per routed row
__device__ int   g_rows[MAX_ROWS];                     // routed row -> token id
__device__ int   g_sel[2 * T_TOK];                     // per token: expert ids (top2)
__device__ float g_tw[2 * T_TOK];                      // per token: combine weights
__device__ int   g_pos[2 * T_TOK];                     // per token: routed row position
__device__ int   g_cnt[E_NUM];
__device__ int   g_cursor[E_NUM];
__device__ int   g_base[E_NUM];
__device__ int   g_tileExpert[MAX_TILES];
__device__ int   g_numTiles;
__device__ float g_psum[1024 * E_NUM];                 // per router-block prob sums

// ---------------- tf32 mma helpers ----------------
__device__ __forceinline__ unsigned f2tf32(float x) {
    unsigned r;
    asm("cvt.rna.tf32.f32 %0, %1;" : "=r"(r) : "f"(x));
    return r;
}

__device__ __forceinline__ void mma_tf32(float* d, const unsigned* a, const unsigned* b) {
    asm volatile(
        "mma.sync.aligned.m16n8k8.row.col.f32.tf32.tf32.f32 "
        "{%0,%1,%2,%3}, {%4,%5,%6,%7}, {%8,%9}, {%0,%1,%2,%3};\n"
        : "+f"(d[0]), "+f"(d[1]), "+f"(d[2]), "+f"(d[3])
        : "r"(a[0]), "r"(a[1]), "r"(a[2]), "r"(a[3]), "r"(b[0]), "r"(b[1]));
}

// ---------------- kernels ----------------
__global__ void k_init() {
    int i = threadIdx.x;
    if (i < E_NUM) { g_cnt[i] = 0; g_cursor[i] = 0; }
}

// One warp per token. gate_w cached in SMEM.
__global__ void __launch_bounds__(256) k_router(const float* __restrict__ x,
                                                const float* __restrict__ gw) {
    __shared__ float s_gw[E_NUM][H_DIM];     // 32 KB
    __shared__ float s_psum[E_NUM];
    int tid = threadIdx.x;
    for (int i = tid; i < E_NUM * H_DIM / 4; i += 256)
        ((float4*)s_gw)[i] = ((const float4*)gw)[i];
    if (tid < E_NUM) s_psum[tid] = 0.f;
    __syncthreads();

    int warp = tid >> 5, lane = tid & 31;
    int t = blockIdx.x * 8 + warp;

    float acc[E_NUM];
#pragma unroll
    for (int e = 0; e < E_NUM; e++) acc[e] = 0.f;

    const float* xr = x + (size_t)t * H_DIM;
    for (int i = lane; i < H_DIM; i += 32) {
        float xv = xr[i];
#pragma unroll
        for (int e = 0; e < E_NUM; e++) acc[e] += xv * s_gw[e][i];
    }
#pragma unroll
    for (int e = 0; e < E_NUM; e++) {
#pragma unroll
        for (int off = 16; off; off >>= 1)
            acc[e] += __shfl_xor_sync(0xFFFFFFFFu, acc[e], off);
    }

    if (lane == 0) {
        float mx = acc[0];
#pragma unroll
        for (int e = 1; e < E_NUM; e++) mx = fmaxf(mx, acc[e]);
        float p[E_NUM], s = 0.f;
#pragma unroll
        for (int e = 0; e < E_NUM; e++) { p[e] = expf(acc[e] - mx); s += p[e]; }
        float inv = 1.f / s;
#pragma unroll
        for (int e = 0; e < E_NUM; e++) p[e] *= inv;

        // top-2 (lowest index wins ties, matching lax.top_k)
        int e0 = 0;
#pragma unroll
        for (int e = 1; e < E_NUM; e++) if (p[e] > p[e0]) e0 = e;
        int e1 = (e0 == 0) ? 1 : 0;
#pragma unroll
        for (int e = 0; e < E_NUM; e++)
            if (e != e0 && p[e] > p[e1]) e1 = e;

        // reference: softmax over the top-2 *probabilities*
        float q0 = expf(p[e0]), q1 = expf(p[e1]);
        float w0 = q0 / (q0 + q1), w1 = q1 / (q0 + q1);

        g_sel[2 * t] = e0; g_sel[2 * t + 1] = e1;
        g_tw[2 * t] = w0;  g_tw[2 * t + 1] = w1;
        atomicAdd(&g_cnt[e0], 1);
        atomicAdd(&g_cnt[e1], 1);
#pragma unroll
        for (int e = 0; e < E_NUM; e++) atomicAdd(&s_psum[e], p[e]);
    }
    __syncthreads();
    if (tid < E_NUM) g_psum[blockIdx.x * E_NUM + tid] = s_psum[tid];
}

// Serial scan over 8 experts: 128-padded bases, tile->expert map, padding fill.
__global__ void k_scan() {
    if (threadIdx.x == 0) {
        int b = 0;
        for (int e = 0; e < E_NUM; e++) {
            g_base[e] = b;
            int cap = (g_cnt[e] + 127) & ~127;
            int t0 = b >> 7, nt = cap >> 7;
            for (int i = 0; i < nt; i++) g_tileExpert[t0 + i] = e;
            b += cap;
        }
        g_numTiles = b >> 7;
    }
    __syncthreads();
    for (int e = 0; e < E_NUM; e++) {
        int c = g_cnt[e], cap = (c + 127) & ~127, b = g_base[e];
        for (int i = c + threadIdx.x; i < cap; i += blockDim.x)
            g_rows[b + i] = 0;   // padding rows: token 0, never combined
    }
}

__global__ void k_scatter() {
    int t = blockIdx.x * 256 + threadIdx.x;
#pragma unroll
    for (int k = 0; k < 2; k++) {
        int e = g_sel[2 * t + k];
        int pos = g_base[e] + atomicAdd(&g_cursor[e], 1);
        g_rows[pos] = t;
        g_pos[2 * t + k] = pos;
    }
}

// Pass 1: H = silu(X @ Wg) * (X @ Wu), per routed 128-row tile, 64 F-cols/block.
__global__ void __launch_bounds__(256, 2) k_ffn1(const float* __restrict__ x,
                                                 const float* __restrict__ Wg,
                                                 const float* __restrict__ Wu) {
    int tile = blockIdx.y;
    if (tile >= g_numTiles) return;
    int e = g_tileExpert[tile];
    int n0 = blockIdx.x * 64;

    __shared__ float sX[32][132];
    __shared__ float sG[32][68];
    __shared__ float sU[32][68];
    __shared__ int   trow[128];

    int tid = threadIdx.x;
    if (tid < 128) trow[tid] = g_rows[tile * 128 + tid];
    __syncthreads();

    int warp = tid >> 5, lane = tid & 31;
    int wm = warp & 3, wn = warp >> 2;
    int g = lane >> 2, q = lane & 3;

    float accG[2][4][4] = {};
    float accU[2][4][4] = {};

    const float* wg0 = Wg + (size_t)e * H_DIM * F_DIM + n0;
    const float* wu0 = Wu + (size_t)e * H_DIM * F_DIM + n0;

    int m = tid & 127, kq = tid >> 7;
    const float* xrow = x + (size_t)trow[m] * H_DIM;

    for (int k0 = 0; k0 < H_DIM; k0 += 32) {
#pragma unroll
        for (int it = 0; it < 4; it++) {
            int k4 = (kq + it * 2) * 4;
            float4 v = *(const float4*)(xrow + k0 + k4);
            sX[k4 + 0][m] = v.x; sX[k4 + 1][m] = v.y;
            sX[k4 + 2][m] = v.z; sX[k4 + 3][m] = v.w;
        }
#pragma unroll
        for (int it = 0; it < 2; it++) {
            int idx = tid + it * 256;
            int kk = idx >> 4, nf4 = (idx & 15) * 4;
            *(float4*)&sG[kk][nf4] = *(const float4*)(wg0 + (size_t)(k0 + kk) * F_DIM + nf4);
            *(float4*)&sU[kk][nf4] = *(const float4*)(wu0 + (size_t)(k0 + kk) * F_DIM + nf4);
        }
        __syncthreads();

#pragma unroll
        for (int ks = 0; ks < 4; ks++) {
            int kb = ks * 8;
            unsigned a[2][4];
#pragma unroll
            for (int mf = 0; mf < 2; mf++) {
                int row = wm * 32 + mf * 16 + g;
                a[mf][0] = f2tf32(sX[kb + q][row]);
                a[mf][1] = f2tf32(sX[kb + q][row + 8]);
                a[mf][2] = f2tf32(sX[kb + q + 4][row]);
                a[mf][3] = f2tf32(sX[kb + q + 4][row + 8]);
            }
#pragma unroll
            for (int nf = 0; nf < 4; nf++) {
                int col = wn * 32 + nf * 8 + g;
                unsigned bg[2], bu[2];
                bg[0] = f2tf32(sG[kb + q][col]); bg[1] = f2tf32(sG[kb + q + 4][col]);
                bu[0] = f2tf32(sU[kb + q][col]); bu[1] = f2tf32(sU[kb + q + 4][col]);
#pragma unroll
                for (int mf = 0; mf < 2; mf++) {
                    mma_tf32(accG[mf][nf], a[mf], bg);
                    mma_tf32(accU[mf][nf], a[mf], bu);
                }
            }
        }
        __syncthreads();
    }

    // epilogue: silu(g)*u -> g_h
#pragma unroll
    for (int mf = 0; mf < 2; mf++) {
#pragma unroll
        for (int nf = 0; nf < 4; nf++) {
            int row = wm * 32 + mf * 16 + g;
            int col = wn * 32 + nf * 8 + 2 * q;
            float* h0 = g_h + (size_t)(tile * 128 + row) * F_DIM + n0 + col;
            float* h1 = g_h + (size_t)(tile * 128 + row + 8) * F_DIM + n0 + col;
            float hg, hu, v0, v1;
            hg = accG[mf][nf][0]; hu = accU[mf][nf][0]; v0 = hg / (1.f + expf(-hg)) * hu;
            hg = accG[mf][nf][1]; hu = accU[mf][nf][1]; v1 = hg / (1.f + expf(-hg)) * hu;
            *(float2*)h0 = make_float2(v0, v1);
            hg = accG[mf][nf][2]; hu = accU[mf][nf][2]; v0 = hg / (1.f + expf(-hg)) * hu;
            hg = accG[mf][nf][3]; hu = accU[mf][nf][3]; v1 = hg / (1.f + expf(-hg)) * hu;
            *(float2*)h1 = make_float2(v0, v1);
        }
    }
}

// Pass 2: partial = H @ Wd[e], 128x128 tiles, K=4096.
__global__ void __launch_bounds__(256, 2) k_ffn2(const float* __restrict__ Wd) {
    int tile = blockIdx.y;
    if (tile >= g_numTiles) return;
    int e = g_tileExpert[tile];
    int n0 = blockIdx.x * 128;

    __shared__ float sH[32][132];
    __shared__ float sW[32][132];

    int tid = threadIdx.x;
    int warp = tid >> 5, lane = tid & 31;
    int wm = warp & 3, wn = warp >> 2;
    int g = lane >> 2, q = lane & 3;

    float acc[2][8][4] = {};

    const float* wd0 = Wd + (size_t)e * F_DIM * H_DIM + n0;
    int m = tid & 127, kq = tid >> 7;
    const float* hrow = g_h + (size_t)(tile * 128 + m) * F_DIM;

    for (int k0 = 0; k0 < F_DIM; k0 += 32) {
#pragma unroll
        for (int it = 0; it < 4; it++) {
            int k4 = (kq + it * 2) * 4;
            float4 v = *(const float4*)(hrow + k0 + k4);
            sH[k4 + 0][m] = v.x; sH[k4 + 1][m] = v.y;
            sH[k4 + 2][m] = v.z; sH[k4 + 3][m] = v.w;
        }
#pragma unroll
        for (int it = 0; it < 4; it++) {
            int idx = tid + it * 256;
            int kk = idx >> 5, nf4 = (idx & 31) * 4;
            *(float4*)&sW[kk][nf4] = *(const float4*)(wd0 + (size_t)(k0 + kk) * H_DIM + nf4);
        }
        __syncthreads();

#pragma unroll
        for (int ks = 0; ks < 4; ks++) {
            int kb = ks * 8;
            unsigned a[2][4];
#pragma unroll
            for (int mf = 0; mf < 2; mf++) {
                int row = wm * 32 + mf * 16 + g;
                a[mf][0] = f2tf32(sH[kb + q][row]);
                a[mf][1] = f2tf32(sH[kb + q][row + 8]);
                a[mf][2] = f2tf32(sH[kb + q + 4][row]);
                a[mf][3] = f2tf32(sH[kb + q + 4][row + 8]);
            }
#pragma unroll
            for (int nf = 0; nf < 8; nf++) {
                int col = wn * 64 + nf * 8 + g;
                unsigned b[2];
                b[0] = f2tf32(sW[kb + q][col]);
                b[1] = f2tf32(sW[kb + q + 4][col]);
#pragma unroll
                for (int mf = 0; mf < 2; mf++)
                    mma_tf32(acc[mf][nf], a[mf], b);
            }
        }
        __syncthreads();
    }

#pragma unroll
    for (int mf = 0; mf < 2; mf++) {
#pragma unroll
        for (int nf = 0; nf < 8; nf++) {
            int row = wm * 32 + mf * 16 + g;
            int col = wn * 64 + nf * 8 + 2 * q;
            float* p0 = g_partial + (size_t)(tile * 128 + row) * H_DIM + n0 + col;
            float* p1 = g_partial + (size_t)(tile * 128 + row + 8) * H_DIM + n0 + col;
            *(float2*)p0 = make_float2(acc[mf][nf][0], acc[mf][nf][1]);
            *(float2*)p1 = make_float2(acc[mf][nf][2], acc[mf][nf][3]);
        }
    }
}

// Deterministic combine: out[t] = w0*partial[pos0] + w1*partial[pos1]
__global__ void __launch_bounds__(256) k_combine(float* __restrict__ out) {
    int idx = blockIdx.x * 256 + threadIdx.x;      // T*H/4 float4s
    int t = idx >> 8;
    int c = (idx & 255) << 2;
    float w0 = g_tw[2 * t], w1 = g_tw[2 * t + 1];
    int p0 = g_pos[2 * t], p1 = g_pos[2 * t + 1];
    float4 a = *(const float4*)(g_partial + (size_t)p0 * H_DIM + c);
    float4 b = *(const float4*)(g_partial + (size_t)p1 * H_DIM + c);
    float4 o;
    o.x = w0 * a.x + w1 * b.x;
    o.y = w0 * a.y + w1 * b.y;
    o.z = w0 * a.z + w1 * b.z;
    o.w = w0 * a.w + w1 * b.w;
    *(float4*)(out + (size_t)t * H_DIM + c) = o;
}

__global__ void k_aux(float* __restrict__ out, int out_size) {
    __shared__ float red[256];
    __shared__ float tot[E_NUM];
    float local[E_NUM];
#pragma unroll
    for (int e = 0; e < E_NUM; e++) local[e] = 0.f;
    for (int b = threadIdx.x; b < 1024; b += 256) {
#pragma unroll
        for (int e = 0; e < E_NUM; e++) local[e] += g_psum[b * E_NUM + e];
    }
    for (int e = 0; e < E_NUM; e++) {
        red[threadIdx.x] = local[e];
        __syncthreads();
        for (int s = 128; s; s >>= 1) {
            if (threadIdx.x < s) red[threadIdx.x] += red[threadIdx.x + s];
            __syncthreads();
        }
        if (threadIdx.x == 0) tot[e] = red[0];
        __syncthreads();
    }
    if (threadIdx.x == 0) {
        float aux = 0.f;
        const float invT = 1.f / (float)T_TOK;
#pragma unroll
        for (int e = 0; e < E_NUM; e++)
            aux += ((float)g_cnt[e] * invT) * (tot[e] * invT);
        aux *= (float)E_NUM;
        if (out_size > T_TOK * H_DIM)
            out[(size_t)T_TOK * H_DIM] = aux;
    }
}

// ---------------- launcher ----------------
extern "C" void kernel_launch(void* const* d_in, const int* in_sizes, int n_in,
                              void* d_out, int out_size) {
    const float* x  = (const float*)d_in[0];
    const float* gw = (const float*)d_in[1];
    const float* Wg = (const float*)d_in[2];
    const float* Wu = (const float*)d_in[3];
    const float* Wd = (const float*)d_in[4];
    float* out = (float*)d_out;

    k_init<<<1, 32>>>();
    k_router<<<T_TOK / 8, 256>>>(x, gw);
    k_scan<<<1, 256>>>();
    k_scatter<<<T_TOK / 256, 256>>>();
    k_ffn1<<<dim3(F_DIM / 64, MAX_TILES), 256>>>(x, Wg, Wu);
    k_ffn2<<<dim3(H_DIM / 128, MAX_TILES), 256>>>(Wd);
    k_combine<<<(T_TOK * H_DIM / 4) / 256, 256>>>(out);
    k_aux<<<1, 256>>>(out, out_size);
}

// round 5
// speedup vs baseline: 1.8055x; 1.8055x over previous
#include <cuda_runtime.h>
#include <math.h>
#include <stdint.h>

// ---------------- problem constants ----------------
#define T_TOK   8192
#define H_DIM   1024
#define E_NUM   8
#define F_DIM   4096
#define MAX_TILES 136              // sum_e ceil(cnt_e/128) <= (16384 + 8*127)/128 < 136
#define MAX_ROWS  (MAX_TILES * 128)

// ---------------- device scratch (no allocations allowed) ----------------
__device__ __align__(128) float g_h[(size_t)MAX_ROWS * F_DIM];        // silu(xWg)*(xWu)
__device__ __align__(128) float g_partial[(size_t)MAX_ROWS * H_DIM];  // down-proj partials
__device__ int   g_rows[MAX_ROWS];
__device__ int   g_sel[2 * T_TOK];
__device__ float g_tw[2 * T_TOK];
__device__ int   g_pos[2 * T_TOK];
__device__ int   g_cnt[E_NUM];
__device__ int   g_cursor[E_NUM];
__device__ int   g_base[E_NUM];
__device__ int   g_tileExpert[MAX_TILES];
__device__ int   g_numTiles;
__device__ float g_psum[1024 * E_NUM];

// ---------------- helpers ----------------
__device__ __forceinline__ unsigned f2tf32(float x) {
    unsigned r;
    asm("cvt.rna.tf32.f32 %0, %1;" : "=r"(r) : "f"(x));
    return r;
}

__device__ __forceinline__ void mma_tf32(float* d, const unsigned* a, const unsigned* b) {
    asm volatile(
        "mma.sync.aligned.m16n8k8.row.col.f32.tf32.tf32.f32 "
        "{%0,%1,%2,%3}, {%4,%5,%6,%7}, {%8,%9}, {%0,%1,%2,%3};\n"
        : "+f"(d[0]), "+f"(d[1]), "+f"(d[2]), "+f"(d[3])
        : "r"(a[0]), "r"(a[1]), "r"(a[2]), "r"(a[3]), "r"(b[0]), "r"(b[1]));
}

__device__ __forceinline__ void cp16(float* smem_dst, const float* gmem_src) {
    unsigned s = (unsigned)__cvta_generic_to_shared(smem_dst);
    asm volatile("cp.async.cg.shared.global [%0], [%1], 16;\n" :: "r"(s), "l"(gmem_src));
}
#define CP_COMMIT()  asm volatile("cp.async.commit_group;\n" ::: "memory")
#define CP_WAIT1()   asm volatile("cp.async.wait_group 1;\n" ::: "memory")
#define CP_WAIT0()   asm volatile("cp.async.wait_group 0;\n" ::: "memory")

// ---------------- small kernels ----------------
__global__ void k_init() {
    int i = threadIdx.x;
    if (i < E_NUM) { g_cnt[i] = 0; g_cursor[i] = 0; }
}

__global__ void __launch_bounds__(256) k_router(const float* __restrict__ x,
                                                const float* __restrict__ gw) {
    __shared__ float s_gw[E_NUM][H_DIM];
    __shared__ float s_psum[E_NUM];
    int tid = threadIdx.x;
    for (int i = tid; i < E_NUM * H_DIM / 4; i += 256)
        ((float4*)s_gw)[i] = ((const float4*)gw)[i];
    if (tid < E_NUM) s_psum[tid] = 0.f;
    __syncthreads();

    int warp = tid >> 5, lane = tid & 31;
    int t = blockIdx.x * 8 + warp;

    float acc[E_NUM];
#pragma unroll
    for (int e = 0; e < E_NUM; e++) acc[e] = 0.f;

    const float* xr = x + (size_t)t * H_DIM;
    for (int i = lane; i < H_DIM; i += 32) {
        float xv = xr[i];
#pragma unroll
        for (int e = 0; e < E_NUM; e++) acc[e] += xv * s_gw[e][i];
    }
#pragma unroll
    for (int e = 0; e < E_NUM; e++) {
#pragma unroll
        for (int off = 16; off; off >>= 1)
            acc[e] += __shfl_xor_sync(0xFFFFFFFFu, acc[e], off);
    }

    if (lane == 0) {
        float mx = acc[0];
#pragma unroll
        for (int e = 1; e < E_NUM; e++) mx = fmaxf(mx, acc[e]);
        float p[E_NUM], s = 0.f;
#pragma unroll
        for (int e = 0; e < E_NUM; e++) { p[e] = expf(acc[e] - mx); s += p[e]; }
        float inv = 1.f / s;
#pragma unroll
        for (int e = 0; e < E_NUM; e++) p[e] *= inv;

        int e0 = 0;
#pragma unroll
        for (int e = 1; e < E_NUM; e++) if (p[e] > p[e0]) e0 = e;
        int e1 = (e0 == 0) ? 1 : 0;
#pragma unroll
        for (int e = 0; e < E_NUM; e++)
            if (e != e0 && p[e] > p[e1]) e1 = e;

        float q0 = expf(p[e0]), q1 = expf(p[e1]);
        float w0 = q0 / (q0 + q1), w1 = q1 / (q0 + q1);

        g_sel[2 * t] = e0; g_sel[2 * t + 1] = e1;
        g_tw[2 * t] = w0;  g_tw[2 * t + 1] = w1;
        atomicAdd(&g_cnt[e0], 1);
        atomicAdd(&g_cnt[e1], 1);
#pragma unroll
        for (int e = 0; e < E_NUM; e++) atomicAdd(&s_psum[e], p[e]);
    }
    __syncthreads();
    if (tid < E_NUM) g_psum[blockIdx.x * E_NUM + tid] = s_psum[tid];
}

__global__ void k_scan() {
    if (threadIdx.x == 0) {
        int b = 0;
        for (int e = 0; e < E_NUM; e++) {
            g_base[e] = b;
            int cap = (g_cnt[e] + 127) & ~127;
            int t0 = b >> 7, nt = cap >> 7;
            for (int i = 0; i < nt; i++) g_tileExpert[t0 + i] = e;
            b += cap;
        }
        g_numTiles = b >> 7;
    }
    __syncthreads();
    for (int e = 0; e < E_NUM; e++) {
        int c = g_cnt[e], cap = (c + 127) & ~127, b = g_base[e];
        for (int i = c + threadIdx.x; i < cap; i += blockDim.x)
            g_rows[b + i] = 0;
    }
}

__global__ void k_scatter() {
    int t = blockIdx.x * 256 + threadIdx.x;
#pragma unroll
    for (int k = 0; k < 2; k++) {
        int e = g_sel[2 * t + k];
        int pos = g_base[e] + atomicAdd(&g_cursor[e], 1);
        g_rows[pos] = t;
        g_pos[2 * t + k] = pos;
    }
}

// ---------------- FFN pass 1: H = silu(X@Wg) * (X@Wu) ----------------
// 128 routed rows x 64 F-cols (G and U each). 2-stage cp.async pipeline.
#define X_PAD 36
#define GU_PAD 72
#define FFN1_SMEM ((2*128*X_PAD + 2*32*GU_PAD + 2*32*GU_PAD) * 4 + 128 * 4)

__global__ void __launch_bounds__(256, 2) k_ffn1(const float* __restrict__ x,
                                                 const float* __restrict__ Wg,
                                                 const float* __restrict__ Wu) {
    extern __shared__ float smem[];
    float* sX = smem;                           // 2*128*36
    float* sG = sX + 2 * 128 * X_PAD;           // 2*32*72
    float* sU = sG + 2 * 32 * GU_PAD;           // 2*32*72
    int* trow = (int*)(sU + 2 * 32 * GU_PAD);   // 128

    int tile = blockIdx.y;
    if (tile >= g_numTiles) return;
    int e = g_tileExpert[tile];
    int n0 = blockIdx.x * 64;
    int tid = threadIdx.x;

    if (tid < 128) trow[tid] = g_rows[tile * 128 + tid];
    __syncthreads();

    const float* xp[4];
    int xo[4];
#pragma unroll
    for (int j = 0; j < 4; j++) {
        int c = tid + j * 256;          // 0..1023
        int row = c >> 3, seg = c & 7;
        xp[j] = x + (size_t)trow[row] * H_DIM + seg * 4;
        xo[j] = row * X_PAD + seg * 4;
    }
    const float* wg0 = Wg + (size_t)e * H_DIM * F_DIM + n0;
    const float* wu0 = Wu + (size_t)e * H_DIM * F_DIM + n0;

    int warp = tid >> 5, lane = tid & 31;
    int wm = warp & 3, wn = warp >> 2;
    int g = lane >> 2, q = lane & 3;

    float accG[2][4][4] = {};
    float accU[2][4][4] = {};

    auto load_stage = [&](int buf, int k0) {
        float* bX = sX + buf * 128 * X_PAD;
        float* bG = sG + buf * 32 * GU_PAD;
        float* bU = sU + buf * 32 * GU_PAD;
#pragma unroll
        for (int j = 0; j < 4; j++)
            cp16(bX + xo[j], xp[j] + k0);
#pragma unroll
        for (int j = 0; j < 2; j++) {
            int c = tid + j * 256;      // 0..511
            int kk = c >> 4, seg = c & 15;
            cp16(bG + kk * GU_PAD + seg * 4, wg0 + (size_t)(k0 + kk) * F_DIM + seg * 4);
            cp16(bU + kk * GU_PAD + seg * 4, wu0 + (size_t)(k0 + kk) * F_DIM + seg * 4);
        }
    };

    load_stage(0, 0);
    CP_COMMIT();

    const int KIT = H_DIM / 32;
    for (int ki = 0; ki < KIT; ki++) {
        int buf = ki & 1;
        if (ki + 1 < KIT) {
            load_stage(buf ^ 1, (ki + 1) * 32);
            CP_COMMIT();
            CP_WAIT1();
        } else {
            CP_WAIT0();
        }
        __syncthreads();

        const float* bX = sX + buf * 128 * X_PAD;
        const float* bG = sG + buf * 32 * GU_PAD;
        const float* bU = sU + buf * 32 * GU_PAD;

#pragma unroll
        for (int ks = 0; ks < 4; ks++) {
            int kb = ks * 8;
            unsigned a[2][4];
#pragma unroll
            for (int mf = 0; mf < 2; mf++) {
                int row = wm * 32 + mf * 16 + g;
                a[mf][0] = f2tf32(bX[row * X_PAD + kb + q]);
                a[mf][1] = f2tf32(bX[(row + 8) * X_PAD + kb + q]);
                a[mf][2] = f2tf32(bX[row * X_PAD + kb + q + 4]);
                a[mf][3] = f2tf32(bX[(row + 8) * X_PAD + kb + q + 4]);
            }
#pragma unroll
            for (int nf = 0; nf < 4; nf++) {
                int col = wn * 32 + nf * 8 + g;
                unsigned bg[2], bu[2];
                bg[0] = f2tf32(bG[(kb + q) * GU_PAD + col]);
                bg[1] = f2tf32(bG[(kb + q + 4) * GU_PAD + col]);
                bu[0] = f2tf32(bU[(kb + q) * GU_PAD + col]);
                bu[1] = f2tf32(bU[(kb + q + 4) * GU_PAD + col]);
#pragma unroll
                for (int mf = 0; mf < 2; mf++) {
                    mma_tf32(accG[mf][nf], a[mf], bg);
                    mma_tf32(accU[mf][nf], a[mf], bu);
                }
            }
        }
        __syncthreads();
    }

#pragma unroll
    for (int mf = 0; mf < 2; mf++) {
#pragma unroll
        for (int nf = 0; nf < 4; nf++) {
            int row = wm * 32 + mf * 16 + g;
            int col = wn * 32 + nf * 8 + 2 * q;
            float* h0 = g_h + (size_t)(tile * 128 + row) * F_DIM + n0 + col;
            float* h1 = g_h + (size_t)(tile * 128 + row + 8) * F_DIM + n0 + col;
            float hg, hu, v0, v1;
            hg = accG[mf][nf][0]; hu = accU[mf][nf][0]; v0 = hg / (1.f + expf(-hg)) * hu;
            hg = accG[mf][nf][1]; hu = accU[mf][nf][1]; v1 = hg / (1.f + expf(-hg)) * hu;
            *(float2*)h0 = make_float2(v0, v1);
            hg = accG[mf][nf][2]; hu = accU[mf][nf][2]; v0 = hg / (1.f + expf(-hg)) * hu;
            hg = accG[mf][nf][3]; hu = accU[mf][nf][3]; v1 = hg / (1.f + expf(-hg)) * hu;
            *(float2*)h1 = make_float2(v0, v1);
        }
    }
}

// ---------------- FFN pass 2: partial = H @ Wd[e] ----------------
#define W_PAD 136
#define FFN2_SMEM ((2*128*X_PAD + 2*32*W_PAD) * 4)

__global__ void __launch_bounds__(256, 2) k_ffn2(const float* __restrict__ Wd) {
    extern __shared__ float smem[];
    float* sH = smem;                         // 2*128*36
    float* sW = sH + 2 * 128 * X_PAD;         // 2*32*136

    int tile = blockIdx.y;
    if (tile >= g_numTiles) return;
    int e = g_tileExpert[tile];
    int n0 = blockIdx.x * 128;
    int tid = threadIdx.x;

    int warp = tid >> 5, lane = tid & 31;
    int wm = warp & 3, wn = warp >> 2;
    int g = lane >> 2, q = lane & 3;

    float acc[2][8][4] = {};

    const float* wd0 = Wd + (size_t)e * F_DIM * H_DIM + n0;
    const float* hbase = g_h + (size_t)tile * 128 * F_DIM;

    auto load_stage = [&](int buf, int k0) {
        float* bH = sH + buf * 128 * X_PAD;
        float* bW = sW + buf * 32 * W_PAD;
#pragma unroll
        for (int j = 0; j < 4; j++) {
            int c = tid + j * 256;      // 0..1023
            int row = c >> 3, seg = c & 7;
            cp16(bH + row * X_PAD + seg * 4, hbase + (size_t)row * F_DIM + k0 + seg * 4);
        }
#pragma unroll
        for (int j = 0; j < 4; j++) {
            int c = tid + j * 256;      // 0..1023
            int kk = c >> 5, seg = c & 31;
            cp16(bW + kk * W_PAD + seg * 4, wd0 + (size_t)(k0 + kk) * H_DIM + seg * 4);
        }
    };

    load_stage(0, 0);
    CP_COMMIT();

    const int KIT = F_DIM / 32;
    for (int ki = 0; ki < KIT; ki++) {
        int buf = ki & 1;
        if (ki + 1 < KIT) {
            load_stage(buf ^ 1, (ki + 1) * 32);
            CP_COMMIT();
            CP_WAIT1();
        } else {
            CP_WAIT0();
        }
        __syncthreads();

        const float* bH = sH + buf * 128 * X_PAD;
        const float* bW = sW + buf * 32 * W_PAD;

#pragma unroll
        for (int ks = 0; ks < 4; ks++) {
            int kb = ks * 8;
            unsigned a[2][4];
#pragma unroll
            for (int mf = 0; mf < 2; mf++) {
                int row = wm * 32 + mf * 16 + g;
                a[mf][0] = f2tf32(bH[row * X_PAD + kb + q]);
                a[mf][1] = f2tf32(bH[(row + 8) * X_PAD + kb + q]);
                a[mf][2] = f2tf32(bH[row * X_PAD + kb + q + 4]);
                a[mf][3] = f2tf32(bH[(row + 8) * X_PAD + kb + q + 4]);
            }
#pragma unroll
            for (int nf = 0; nf < 8; nf++) {
                int col = wn * 64 + nf * 8 + g;
                unsigned b[2];
                b[0] = f2tf32(bW[(kb + q) * W_PAD + col]);
                b[1] = f2tf32(bW[(kb + q + 4) * W_PAD + col]);
#pragma unroll
                for (int mf = 0; mf < 2; mf++)
                    mma_tf32(acc[mf][nf], a[mf], b);
            }
        }
        __syncthreads();
    }

#pragma unroll
    for (int mf = 0; mf < 2; mf++) {
#pragma unroll
        for (int nf = 0; nf < 8; nf++) {
            int row = wm * 32 + mf * 16 + g;
            int col = wn * 64 + nf * 8 + 2 * q;
            float* p0 = g_partial + (size_t)(tile * 128 + row) * H_DIM + n0 + col;
            float* p1 = g_partial + (size_t)(tile * 128 + row + 8) * H_DIM + n0 + col;
            *(float2*)p0 = make_float2(acc[mf][nf][0], acc[mf][nf][1]);
            *(float2*)p1 = make_float2(acc[mf][nf][2], acc[mf][nf][3]);
        }
    }
}

// ---------------- combine + aux ----------------
__global__ void __launch_bounds__(256) k_combine(float* __restrict__ out) {
    int idx = blockIdx.x * 256 + threadIdx.x;
    int t = idx >> 8;
    int c = (idx & 255) << 2;
    float w0 = g_tw[2 * t], w1 = g_tw[2 * t + 1];
    int p0 = g_pos[2 * t], p1 = g_pos[2 * t + 1];
    float4 a = *(const float4*)(g_partial + (size_t)p0 * H_DIM + c);
    float4 b = *(const float4*)(g_partial + (size_t)p1 * H_DIM + c);
    float4 o;
    o.x = w0 * a.x + w1 * b.x;
    o.y = w0 * a.y + w1 * b.y;
    o.z = w0 * a.z + w1 * b.z;
    o.w = w0 * a.w + w1 * b.w;
    *(float4*)(out + (size_t)t * H_DIM + c) = o;
}

__global__ void k_aux(float* __restrict__ out, int out_size) {
    __shared__ float red[256];
    __shared__ float tot[E_NUM];
    float local[E_NUM];
#pragma unroll
    for (int e = 0; e < E_NUM; e++) local[e] = 0.f;
    for (int b = threadIdx.x; b < 1024; b += 256) {
#pragma unroll
        for (int e = 0; e < E_NUM; e++) local[e] += g_psum[b * E_NUM + e];
    }
    for (int e = 0; e < E_NUM; e++) {
        red[threadIdx.x] = local[e];
        __syncthreads();
        for (int s = 128; s; s >>= 1) {
            if (threadIdx.x < s) red[threadIdx.x] += red[threadIdx.x + s];
            __syncthreads();
        }
        if (threadIdx.x == 0) tot[e] = red[0];
        __syncthreads();
    }
    if (threadIdx.x == 0) {
        float aux = 0.f;
        const float invT = 1.f / (float)T_TOK;
#pragma unroll
        for (int e = 0; e < E_NUM; e++)
            aux += ((float)g_cnt[e] * invT) * (tot[e] * invT);
        aux *= (float)E_NUM;
        if (out_size > T_TOK * H_DIM)
            out[(size_t)T_TOK * H_DIM] = aux;
    }
}

// ---------------- launcher ----------------
extern "C" void kernel_launch(void* const* d_in, const int* in_sizes, int n_in,
                              void* d_out, int out_size) {
    const float* x  = (const float*)d_in[0];
    const float* gw = (const float*)d_in[1];
    const float* Wg = (const float*)d_in[2];
    const float* Wu = (const float*)d_in[3];
    const float* Wd = (const float*)d_in[4];
    float* out = (float*)d_out;

    (void)cudaFuncSetAttribute(k_ffn1, cudaFuncAttributeMaxDynamicSharedMemorySize, FFN1_SMEM);
    (void)cudaFuncSetAttribute(k_ffn2, cudaFuncAttributeMaxDynamicSharedMemorySize, FFN2_SMEM);

    k_init<<<1, 32>>>();
    k_router<<<T_TOK / 8, 256>>>(x, gw);
    k_scan<<<1, 256>>>();
    k_scatter<<<T_TOK / 256, 256>>>();
    k_ffn1<<<dim3(F_DIM / 64, MAX_TILES), 256, FFN1_SMEM>>>(x, Wg, Wu);
    k_ffn2<<<dim3(H_DIM / 128, MAX_TILES), 256, FFN2_SMEM>>>(Wd);
    k_combine<<<(T_TOK * H_DIM / 4) / 256, 256>>>(out);
    k_aux<<<1, 256>>>(out, out_size);
}